// round 13
// baseline (speedup 1.0000x reference)
#include <cuda_runtime.h>
#include <cuda_bf16.h>
#include <math.h>
#include <stdint.h>

#define B_  4
#define S_  2048
#define D_  1024
#define H_  16
#define HD_ 64
#define NROW (B_*S_)          // 8192

#define TK      64
#define NCHUNK  (D_/TK)       // 16
#define TILE_B  16384         // bytes per 128-row x 128B tile

#define QSCALE 0.1803368801111601f   // 0.125 * log2(e)

// ---------------- scratch (static device globals; no allocation) ------------
__device__ __align__(128) __nv_bfloat16 g_xh[NROW * D_];
__device__ __align__(128) __nv_bfloat16 g_xl[NROW * D_];
__device__ __align__(128) __nv_bfloat16 g_ch[NROW * D_];
__device__ __align__(128) __nv_bfloat16 g_cl[NROW * D_];
__device__ __align__(128) __nv_bfloat16 g_wqh[D_ * D_];
__device__ __align__(128) __nv_bfloat16 g_wql[D_ * D_];
__device__ __align__(128) __nv_bfloat16 g_wkh[D_ * D_];
__device__ __align__(128) __nv_bfloat16 g_wkl[D_ * D_];
__device__ __align__(128) __nv_bfloat16 g_wvh[D_ * D_];
__device__ __align__(128) __nv_bfloat16 g_wvl[D_ * D_];
__device__ __align__(128) __nv_bfloat16 g_woh[D_ * D_];
__device__ __align__(128) __nv_bfloat16 g_wol[D_ * D_];
__device__ __align__(128) __nv_bfloat16 g_qh[NROW * D_];
__device__ __align__(128) __nv_bfloat16 g_ql[NROW * D_];
__device__ __align__(128) __nv_bfloat16 g_kh[NROW * D_];
__device__ __align__(128) __nv_bfloat16 g_kl[NROW * D_];
__device__ __align__(128) __nv_bfloat16 g_vh[NROW * D_];
__device__ __align__(128) __nv_bfloat16 g_vl[NROW * D_];

// ---------------------------- helpers ---------------------------------------
__device__ __forceinline__ uint32_t smem_u32(const void* p) {
    uint32_t a;
    asm("{ .reg .u64 t; cvta.to.shared.u64 t, %1; cvt.u32.u64 %0, t; }"
        : "=r"(a) : "l"(p));
    return a;
}
__host__ __device__ __forceinline__ uint32_t swz128(uint32_t o) {
    return o ^ ((o >> 3) & 0x70);
}
__device__ __forceinline__ void cp16(uint32_t dst, const void* src) {
    asm volatile("cp.async.cg.shared.global [%0], [%1], 16;"
                 :: "r"(dst), "l"(src) : "memory");
}
__device__ __forceinline__ void cp_commit() {
    asm volatile("cp.async.commit_group;" ::: "memory");
}
template <int N>
__device__ __forceinline__ void cp_wait() {
    asm volatile("cp.async.wait_group %0;" :: "n"(N) : "memory");
}
__device__ __forceinline__ void ldm_x4(uint32_t* r, uint32_t addr) {
    asm volatile("ldmatrix.sync.aligned.m8n8.x4.shared.b16 {%0,%1,%2,%3}, [%4];"
                 : "=r"(r[0]), "=r"(r[1]), "=r"(r[2]), "=r"(r[3]) : "r"(addr));
}
__device__ __forceinline__ void ldm_x4t(uint32_t* r, uint32_t addr) {
    asm volatile("ldmatrix.sync.aligned.m8n8.x4.trans.shared.b16 {%0,%1,%2,%3}, [%4];"
                 : "=r"(r[0]), "=r"(r[1]), "=r"(r[2]), "=r"(r[3]) : "r"(addr));
}
__device__ __forceinline__ void mma16816(float* c, const uint32_t* a,
                                         const uint32_t* b) {
    asm volatile(
        "mma.sync.aligned.m16n8k16.row.col.f32.bf16.bf16.f32 "
        "{%0,%1,%2,%3}, {%4,%5,%6,%7}, {%8,%9}, {%0,%1,%2,%3};"
        : "+f"(c[0]), "+f"(c[1]), "+f"(c[2]), "+f"(c[3])
        : "r"(a[0]), "r"(a[1]), "r"(a[2]), "r"(a[3]), "r"(b[0]), "r"(b[1]));
}
__device__ __forceinline__ float ex2(float x) {
    float y;
    asm("ex2.approx.ftz.f32 %0, %1;" : "=f"(y) : "f"(x));
    return y;
}
__device__ __forceinline__ void split2(float a, float b, uint32_t& hi, uint32_t& lo) {
    __nv_bfloat16 ah = __float2bfloat16(a), bh = __float2bfloat16(b);
    __nv_bfloat16 al = __float2bfloat16(a - __bfloat162float(ah));
    __nv_bfloat16 bl = __float2bfloat16(b - __bfloat162float(bh));
    hi = ((uint32_t)__bfloat16_as_ushort(bh) << 16) | __bfloat16_as_ushort(ah);
    lo = ((uint32_t)__bfloat16_as_ushort(bl) << 16) | __bfloat16_as_ushort(al);
}

// ---------------------------------------------------------------------------
// Conversions
// ---------------------------------------------------------------------------
__global__ __launch_bounds__(256) void conv_act(const float* __restrict__ in,
                                                __nv_bfloat16* __restrict__ oh,
                                                __nv_bfloat16* __restrict__ ol)
{
    const int base = blockIdx.x * 256 + threadIdx.x;   // grid 2048 -> 524288
#pragma unroll
    for (int jj = 0; jj < 2; jj++) {
        int idx = base + jj * 524288;
        int R  = idx >> 7, cb = idx & 127;
        int rb = R >> 7,  r  = R & 127;
        int kc = cb >> 3, cc = cb & 7;
        const float* p = in + (size_t)R * D_ + cb * 8;
        float4 a = *(const float4*)p;
        float4 b = *(const float4*)(p + 4);
        float v[8] = {a.x, a.y, a.z, a.w, b.x, b.y, b.z, b.w};
        union { __nv_bfloat16 h[8]; uint4 u; } uh, ul;
#pragma unroll
        for (int j = 0; j < 8; j++) {
            __nv_bfloat16 hb = __float2bfloat16(v[j]);
            uh.h[j] = hb;
            ul.h[j] = __float2bfloat16(v[j] - __bfloat162float(hb));
        }
        uint32_t off = (uint32_t)(rb * NCHUNK + kc) * TILE_B + swz128(r * 128 + cc * 16);
        *(uint4*)((char*)oh + off) = uh.u;
        *(uint4*)((char*)ol + off) = ul.u;
    }
}

__global__ __launch_bounds__(256) void conv_w4(
    const float* __restrict__ W0, const float* __restrict__ W1,
    const float* __restrict__ W2, const float* __restrict__ W3,
    __nv_bfloat16* __restrict__ o0h, __nv_bfloat16* __restrict__ o0l,
    __nv_bfloat16* __restrict__ o1h, __nv_bfloat16* __restrict__ o1l,
    __nv_bfloat16* __restrict__ o2h, __nv_bfloat16* __restrict__ o2l,
    __nv_bfloat16* __restrict__ o3h, __nv_bfloat16* __restrict__ o3l)
{
    const int wsel = blockIdx.y;
    const float* W = (wsel == 0) ? W0 : (wsel == 1) ? W1 : (wsel == 2) ? W2 : W3;
    __nv_bfloat16* oh = (wsel == 0) ? o0h : (wsel == 1) ? o1h : (wsel == 2) ? o2h : o3h;
    __nv_bfloat16* ol = (wsel == 0) ? o0l : (wsel == 1) ? o1l : (wsel == 2) ? o2l : o3l;

    int idx = blockIdx.x * 256 + threadIdx.x;
    int n  = idx & 1023, kb = idx >> 10;
    float v[8];
#pragma unroll
    for (int j = 0; j < 8; j++) v[j] = W[(size_t)(kb * 8 + j) * D_ + n];
    union { __nv_bfloat16 h[8]; uint4 u; } uh, ul;
#pragma unroll
    for (int j = 0; j < 8; j++) {
        __nv_bfloat16 hb = __float2bfloat16(v[j]);
        uh.h[j] = hb;
        ul.h[j] = __float2bfloat16(v[j] - __bfloat162float(hb));
    }
    int tb = n >> 7, r = n & 127, kc = kb >> 3, cc = kb & 7;
    uint32_t off = (uint32_t)(tb * NCHUNK + kc) * TILE_B + swz128(r * 128 + cc * 16);
    *(uint4*)((char*)oh + off) = uh.u;
    *(uint4*)((char*)ol + off) = ul.u;
}

// ---------------------------------------------------------------------------
// GEMM core — hi/lo-granularity double buffering, occ=2 at 96KB.
// Buffers: H0/H1 = {AH,BH} 32KB (double-buffered), L = {AL,BL} 32KB (single).
// Chunk c: pass0 (ah*bh) on prefetched H(c) while lo(c) lands;
//          hi(c+1) issued after pass0, hidden behind pass1 (ah*bl) + pass2 (al*bh).
// ---------------------------------------------------------------------------
#define GSM_BYTES (6 * TILE_B)   // 98304

__device__ __forceinline__ void gemm_core(
    uint32_t S0,
    const char* gAh, const char* gAl, const char* gBh, const char* gBl,
    int tid, int wid, int lane, float acc[4][4][4])
{
    const int wm = wid >> 2, wn = wid & 3;
    const uint32_t LA = S0 + 65536, LB = S0 + 81920;

    const int a_row = wm * 64 + (lane & 15);
    const int a_cb0 = (lane >> 4) * 16;
    const int b_idx = lane >> 3;
    const int b_row = wn * 32 + ((b_idx >> 1) * 8) + (lane & 7);
    const int b_cb0 = (b_idx & 1) * 16;

    // prologue: hi(0) into H stage 0
#pragma unroll
    for (int i = tid; i < 1024; i += 256) {
        cp16(S0 + i * 16,         gAh + i * 16);
        cp16(S0 + 16384 + i * 16, gBh + i * 16);
    }
    cp_commit();

    for (int c = 0; c < NCHUNK; c++) {
        const uint32_t HA = S0 + (uint32_t)(c & 1) * 32768;
        const uint32_t HB = HA + 16384;
        const uint32_t cofs = (uint32_t)c * TILE_B;

        if (c) __syncthreads();   // chunk c-1 fully consumed (L and H[other] free)

        // issue lo(c) into L       outstanding: hi(c), lo(c)
#pragma unroll
        for (int i = tid; i < 1024; i += 256) {
            cp16(LA + i * 16, gAl + cofs + i * 16);
            cp16(LB + i * 16, gBl + cofs + i * 16);
        }
        cp_commit();
        cp_wait<1>();             // hi(c) landed
        __syncthreads();

        // ---- pass0: ah * bh ----
#pragma unroll
        for (int ks = 0; ks < 4; ks++) {
            uint32_t af[4][4], bf[4][2];
            const uint32_t acb = ks * 32 + a_cb0;
            const uint32_t bcb = ks * 32 + b_cb0;
#pragma unroll
            for (int i = 0; i < 4; i++)
                ldm_x4(af[i], HA + swz128((uint32_t)(a_row + i * 16) * 128 + acb));
#pragma unroll
            for (int jp = 0; jp < 2; jp++) {
                uint32_t t4[4];
                ldm_x4(t4, HB + swz128((uint32_t)(b_row + jp * 16) * 128 + bcb));
                bf[jp * 2 + 0][0] = t4[0]; bf[jp * 2 + 0][1] = t4[1];
                bf[jp * 2 + 1][0] = t4[2]; bf[jp * 2 + 1][1] = t4[3];
            }
#pragma unroll
            for (int i = 0; i < 4; i++)
#pragma unroll
                for (int j = 0; j < 4; j++) mma16816(acc[i][j], af[i], bf[j]);
        }

        // prefetch hi(c+1) into H[other]   outstanding: lo(c), hi(c+1)
        if (c + 1 < NCHUNK) {
            const uint32_t H2 = S0 + (uint32_t)((c + 1) & 1) * 32768;
            const uint32_t cofs2 = (uint32_t)(c + 1) * TILE_B;
#pragma unroll
            for (int i = tid; i < 1024; i += 256) {
                cp16(H2 + i * 16,         gAh + cofs2 + i * 16);
                cp16(H2 + 16384 + i * 16, gBh + cofs2 + i * 16);
            }
            cp_commit();
            cp_wait<1>();         // lo(c) landed
        } else {
            cp_wait<0>();
        }
        __syncthreads();

        // ---- pass1: ah * bl ----
#pragma unroll
        for (int ks = 0; ks < 4; ks++) {
            uint32_t af[4][4], bf[4][2];
            const uint32_t acb = ks * 32 + a_cb0;
            const uint32_t bcb = ks * 32 + b_cb0;
#pragma unroll
            for (int i = 0; i < 4; i++)
                ldm_x4(af[i], HA + swz128((uint32_t)(a_row + i * 16) * 128 + acb));
#pragma unroll
            for (int jp = 0; jp < 2; jp++) {
                uint32_t t4[4];
                ldm_x4(t4, LB + swz128((uint32_t)(b_row + jp * 16) * 128 + bcb));
                bf[jp * 2 + 0][0] = t4[0]; bf[jp * 2 + 0][1] = t4[1];
                bf[jp * 2 + 1][0] = t4[2]; bf[jp * 2 + 1][1] = t4[3];
            }
#pragma unroll
            for (int i = 0; i < 4; i++)
#pragma unroll
                for (int j = 0; j < 4; j++) mma16816(acc[i][j], af[i], bf[j]);
        }

        // ---- pass2: al * bh ----
#pragma unroll
        for (int ks = 0; ks < 4; ks++) {
            uint32_t af[4][4], bf[4][2];
            const uint32_t acb = ks * 32 + a_cb0;
            const uint32_t bcb = ks * 32 + b_cb0;
#pragma unroll
            for (int i = 0; i < 4; i++)
                ldm_x4(af[i], LA + swz128((uint32_t)(a_row + i * 16) * 128 + acb));
#pragma unroll
            for (int jp = 0; jp < 2; jp++) {
                uint32_t t4[4];
                ldm_x4(t4, HB + swz128((uint32_t)(b_row + jp * 16) * 128 + bcb));
                bf[jp * 2 + 0][0] = t4[0]; bf[jp * 2 + 0][1] = t4[1];
                bf[jp * 2 + 1][0] = t4[2]; bf[jp * 2 + 1][1] = t4[3];
            }
#pragma unroll
            for (int i = 0; i < 4; i++)
#pragma unroll
                for (int j = 0; j < 4; j++) mma16816(acc[i][j], af[i], bf[j]);
        }
    }
}

// Q/K/V in one launch: blockIdx.z selects weight + destination (+Q scale)
__global__ __launch_bounds__(256, 2) void gemm_qkv(
    const __nv_bfloat16* __restrict__ Ah, const __nv_bfloat16* __restrict__ Al,
    const __nv_bfloat16* __restrict__ wqh, const __nv_bfloat16* __restrict__ wql,
    const __nv_bfloat16* __restrict__ wkh, const __nv_bfloat16* __restrict__ wkl,
    const __nv_bfloat16* __restrict__ wvh, const __nv_bfloat16* __restrict__ wvl,
    __nv_bfloat16* __restrict__ qh, __nv_bfloat16* __restrict__ ql,
    __nv_bfloat16* __restrict__ kh, __nv_bfloat16* __restrict__ kl,
    __nv_bfloat16* __restrict__ vh, __nv_bfloat16* __restrict__ vl)
{
    extern __shared__ char sm[];
    const uint32_t S0 = smem_u32(sm);
    const int tid  = threadIdx.x;
    const int wid  = tid >> 5;
    const int lane = tid & 31;
    const int tb   = blockIdx.x;
    const int rb   = blockIdx.y;
    const int z    = blockIdx.z;

    const __nv_bfloat16 *Bh, *Bl;
    __nv_bfloat16 *Ch, *Cl;
    float osc;
    if (z == 0)      { Bh = wqh; Bl = wql; Ch = qh; Cl = ql; osc = QSCALE; }
    else if (z == 1) { Bh = wkh; Bl = wkl; Ch = kh; Cl = kl; osc = 1.0f; }
    else             { Bh = wvh; Bl = wvl; Ch = vh; Cl = vl; osc = 1.0f; }

    float acc[4][4][4];
#pragma unroll
    for (int i = 0; i < 4; i++)
#pragma unroll
        for (int j = 0; j < 4; j++)
#pragma unroll
            for (int r = 0; r < 4; r++) acc[i][j][r] = 0.f;

    gemm_core(S0,
              (const char*)Ah + (size_t)rb * NCHUNK * TILE_B,
              (const char*)Al + (size_t)rb * NCHUNK * TILE_B,
              (const char*)Bh + (size_t)tb * NCHUNK * TILE_B,
              (const char*)Bl + (size_t)tb * NCHUNK * TILE_B,
              tid, wid, lane, acc);

    const int wm = wid >> 2, wn = wid & 3;
    const int row0 = rb * 128 + wm * 64 + (lane >> 2);
    const int col0 = tb * 128 + wn * 32 + (lane & 3) * 2;
#pragma unroll
    for (int i = 0; i < 4; i++)
#pragma unroll
        for (int j = 0; j < 4; j++) {
            const int cc = col0 + j * 8;
            uint32_t h0, l0, h1, l1;
            split2(acc[i][j][0] * osc, acc[i][j][1] * osc, h0, l0);
            split2(acc[i][j][2] * osc, acc[i][j][3] * osc, h1, l1);
            size_t p0 = ((size_t)(row0 + i * 16) * D_ + cc) * 2;
            size_t p1 = ((size_t)(row0 + i * 16 + 8) * D_ + cc) * 2;
            *(uint32_t*)((char*)Ch + p0) = h0;
            *(uint32_t*)((char*)Cl + p0) = l0;
            *(uint32_t*)((char*)Ch + p1) = h1;
            *(uint32_t*)((char*)Cl + p1) = l1;
        }
}

// output projection: fp32 epilogue + bias
__global__ __launch_bounds__(256, 2) void gemm_out(
    const __nv_bfloat16* __restrict__ Ah, const __nv_bfloat16* __restrict__ Al,
    const __nv_bfloat16* __restrict__ Bh, const __nv_bfloat16* __restrict__ Bl,
    const float* __restrict__ bias, float* __restrict__ C)
{
    extern __shared__ char sm[];
    const uint32_t S0 = smem_u32(sm);
    const int tid  = threadIdx.x;
    const int wid  = tid >> 5;
    const int lane = tid & 31;
    const int tb   = blockIdx.x;
    const int rb   = blockIdx.y;

    float acc[4][4][4];
#pragma unroll
    for (int i = 0; i < 4; i++)
#pragma unroll
        for (int j = 0; j < 4; j++)
#pragma unroll
            for (int r = 0; r < 4; r++) acc[i][j][r] = 0.f;

    gemm_core(S0,
              (const char*)Ah + (size_t)rb * NCHUNK * TILE_B,
              (const char*)Al + (size_t)rb * NCHUNK * TILE_B,
              (const char*)Bh + (size_t)tb * NCHUNK * TILE_B,
              (const char*)Bl + (size_t)tb * NCHUNK * TILE_B,
              tid, wid, lane, acc);

    const int wm = wid >> 2, wn = wid & 3;
    const int row0 = rb * 128 + wm * 64 + (lane >> 2);
    const int col0 = tb * 128 + wn * 32 + (lane & 3) * 2;
#pragma unroll
    for (int i = 0; i < 4; i++)
#pragma unroll
        for (int j = 0; j < 4; j++) {
            const int cc = col0 + j * 8;
            const float b0 = bias[cc], b1 = bias[cc + 1];
            float* p0 = C + (size_t)(row0 + i * 16) * D_ + cc;
            float* p1 = C + (size_t)(row0 + i * 16 + 8) * D_ + cc;
            *(float2*)p0 = make_float2(acc[i][j][0] + b0, acc[i][j][1] + b1);
            *(float2*)p1 = make_float2(acc[i][j][2] + b0, acc[i][j][3] + b1);
        }
}

// ---------------------------------------------------------------------------
// Flash attention on mma.sync (unchanged — known-good, 347us).
// ---------------------------------------------------------------------------
#define FSMEM (32768 + 65536)

__device__ __forceinline__ void fa_load_stage(
    uint32_t sst, int st, int jb, int tid, size_t rowoff_base,
    const __nv_bfloat16* kh, const __nv_bfloat16* kl,
    const __nv_bfloat16* vh, const __nv_bfloat16* vl)
{
    const int r  = tid >> 2;
    const int u0 = (tid & 3) * 2;
    const size_t rowoff = rowoff_base + (size_t)(jb * 64 + r) * 2048;
    const uint32_t base = sst + st * 32768;
    const char* s0 = (const char*)kh + rowoff;
    const char* s1 = (const char*)kl + rowoff;
    const char* s2 = (const char*)vh + rowoff;
    const char* s3 = (const char*)vl + rowoff;
#pragma unroll
    for (int uu = 0; uu < 2; uu++) {
        const uint32_t d = swz128(r * 128 + (u0 + uu) * 16);
        const int sb = (u0 + uu) * 16;
        cp16(base + 0 * 8192 + d, s0 + sb);
        cp16(base + 1 * 8192 + d, s1 + sb);
        cp16(base + 2 * 8192 + d, s2 + sb);
        cp16(base + 3 * 8192 + d, s3 + sb);
    }
}

__global__ __launch_bounds__(256, 2) void flash_mma(
    const __nv_bfloat16* __restrict__ qh, const __nv_bfloat16* __restrict__ ql,
    const __nv_bfloat16* __restrict__ kh, const __nv_bfloat16* __restrict__ kl,
    const __nv_bfloat16* __restrict__ vh, const __nv_bfloat16* __restrict__ vl,
    __nv_bfloat16* __restrict__ ch, __nv_bfloat16* __restrict__ cl)
{
    extern __shared__ char sm[];
    const uint32_t SQH = smem_u32(sm);
    const uint32_t SQL = SQH + 16384;
    const uint32_t SST = SQL + 16384;

    const int tid  = threadIdx.x;
    const int w    = tid >> 5;
    const int lane = tid & 31;
    const int qb   = 15 - blockIdx.x;
    const int h    = blockIdx.y;
    const int b    = blockIdx.z;
    const int qbase = qb * 128;
    const size_t seqoff = ((size_t)b * 2048) * 2048 + (size_t)h * 128;

    {
        const int r  = tid >> 1;
        const int u0 = (tid & 1) * 4;
        const size_t ro = seqoff + (size_t)(qbase + r) * 2048;
        const char* sh = (const char*)qh + ro;
        const char* slo = (const char*)ql + ro;
#pragma unroll
        for (int u = u0; u < u0 + 4; u++) {
            const uint32_t d = swz128(r * 128 + u * 16);
            cp16(SQH + d, sh + u * 16);
            cp16(SQL + d, slo + u * 16);
        }
    }
    cp_commit();

    const int nkb = 2 * qb + 2;
    fa_load_stage(SST, 0, 0, tid, seqoff, kh, kl, vh, vl);
    cp_commit();
    cp_wait<0>();
    __syncthreads();

    uint32_t aqh[4][4], aql[4][4];
    {
        const int ar = w * 16 + (lane & 15);
        const int acb = (lane >> 4) * 16;
#pragma unroll
        for (int kt = 0; kt < 4; kt++) {
            const uint32_t off = swz128((uint32_t)ar * 128 + kt * 32 + acb);
            ldm_x4(aqh[kt], SQH + off);
            ldm_x4(aql[kt], SQL + off);
        }
    }

    float o[8][4];
#pragma unroll
    for (int n = 0; n < 8; n++)
#pragma unroll
        for (int r = 0; r < 4; r++) o[n][r] = 0.f;
    float m0 = -INFINITY, m1 = -INFINITY, l0 = 0.f, l1 = 0.f;

    const int wrow0 = qbase + w * 16;

    for (int jb = 0; jb < nkb; jb++) {
        if (jb + 1 < nkb) {
            fa_load_stage(SST, (jb + 1) & 1, jb + 1, tid, seqoff, kh, kl, vh, vl);
            cp_commit();
            cp_wait<1>();
        } else {
            cp_wait<0>();
        }
        __syncthreads();

        const int kbase = jb * 64;
        if (kbase <= wrow0 + 15) {
            const uint32_t base = SST + (uint32_t)(jb & 1) * 32768;
            const uint32_t KH = base, KL = base + 8192;
            const uint32_t VH = base + 16384, VL = base + 24576;

            float sacc[8][4];
#pragma unroll
            for (int n = 0; n < 8; n++)
#pragma unroll
                for (int r = 0; r < 4; r++) sacc[n][r] = 0.f;

            const uint32_t krow = ((lane >> 4) & 1) * 8 + (lane & 7);
            const uint32_t kcb  = ((lane >> 3) & 1) * 16;
#pragma unroll
            for (int kt = 0; kt < 4; kt++) {
#pragma unroll
                for (int ntp = 0; ntp < 4; ntp++) {
                    const uint32_t off =
                        swz128((ntp * 16 + krow) * 128 + kt * 32 + kcb);
                    uint32_t bh4[4], bl4[4];
                    ldm_x4(bh4, KH + off);
                    ldm_x4(bl4, KL + off);
                    mma16816(sacc[2 * ntp],     aqh[kt], bh4 + 0);
                    mma16816(sacc[2 * ntp],     aqh[kt], bl4 + 0);
                    mma16816(sacc[2 * ntp],     aql[kt], bh4 + 0);
                    mma16816(sacc[2 * ntp + 1], aqh[kt], bh4 + 2);
                    mma16816(sacc[2 * ntp + 1], aqh[kt], bl4 + 2);
                    mma16816(sacc[2 * ntp + 1], aql[kt], bh4 + 2);
                }
            }

            if (kbase + 63 > wrow0) {
                const int rg = wrow0 + (lane >> 2);
#pragma unroll
                for (int nt = 0; nt < 8; nt++) {
                    const int cg = kbase + nt * 8 + (lane & 3) * 2;
                    if (cg     > rg)     sacc[nt][0] = -INFINITY;
                    if (cg + 1 > rg)     sacc[nt][1] = -INFINITY;
                    if (cg     > rg + 8) sacc[nt][2] = -INFINITY;
                    if (cg + 1 > rg + 8) sacc[nt][3] = -INFINITY;
                }
            }

            float nm0 = m0, nm1 = m1;
#pragma unroll
            for (int nt = 0; nt < 8; nt++) {
                nm0 = fmaxf(nm0, fmaxf(sacc[nt][0], sacc[nt][1]));
                nm1 = fmaxf(nm1, fmaxf(sacc[nt][2], sacc[nt][3]));
            }
            nm0 = fmaxf(nm0, __shfl_xor_sync(0xffffffffu, nm0, 1));
            nm0 = fmaxf(nm0, __shfl_xor_sync(0xffffffffu, nm0, 2));
            nm1 = fmaxf(nm1, __shfl_xor_sync(0xffffffffu, nm1, 1));
            nm1 = fmaxf(nm1, __shfl_xor_sync(0xffffffffu, nm1, 2));

            const float sc0 = ex2(m0 - nm0);
            const float sc1 = ex2(m1 - nm1);
            m0 = nm0; m1 = nm1;
            l0 *= sc0; l1 *= sc1;
#pragma unroll
            for (int nt = 0; nt < 8; nt++) {
                o[nt][0] *= sc0; o[nt][1] *= sc0;
                o[nt][2] *= sc1; o[nt][3] *= sc1;
            }

            float rs0 = 0.f, rs1 = 0.f;
            uint32_t ph[4][4], pl[4][4];
#pragma unroll
            for (int t = 0; t < 4; t++) {
#pragma unroll
                for (int hh = 0; hh < 2; hh++) {
                    const int nt = 2 * t + hh;
                    const float p0 = ex2(sacc[nt][0] - nm0);
                    const float p1 = ex2(sacc[nt][1] - nm0);
                    const float p2 = ex2(sacc[nt][2] - nm1);
                    const float p3 = ex2(sacc[nt][3] - nm1);
                    rs0 += p0 + p1; rs1 += p2 + p3;
                    split2(p0, p1, ph[t][2 * hh + 0], pl[t][2 * hh + 0]);
                    split2(p2, p3, ph[t][2 * hh + 1], pl[t][2 * hh + 1]);
                }
            }
            rs0 += __shfl_xor_sync(0xffffffffu, rs0, 1);
            rs0 += __shfl_xor_sync(0xffffffffu, rs0, 2);
            rs1 += __shfl_xor_sync(0xffffffffu, rs1, 1);
            rs1 += __shfl_xor_sync(0xffffffffu, rs1, 2);
            l0 += rs0; l1 += rs1;

            const uint32_t vrow = lane & 15;
            const uint32_t vcg  = lane >> 4;
#pragma unroll
            for (int kt = 0; kt < 4; kt++) {
#pragma unroll
                for (int ntp = 0; ntp < 4; ntp++) {
                    const uint32_t off =
                        swz128((kt * 16 + vrow) * 128 + (2 * ntp + vcg) * 16);
                    uint32_t vbh[4], vbl[4];
                    ldm_x4t(vbh, VH + off);
                    ldm_x4t(vbl, VL + off);
                    mma16816(o[2 * ntp],     ph[kt], vbh + 0);
                    mma16816(o[2 * ntp],     ph[kt], vbl + 0);
                    mma16816(o[2 * ntp],     pl[kt], vbh + 0);
                    mma16816(o[2 * ntp + 1], ph[kt], vbh + 2);
                    mma16816(o[2 * ntp + 1], ph[kt], vbl + 2);
                    mma16816(o[2 * ntp + 1], pl[kt], vbh + 2);
                }
            }
        }
        __syncthreads();
    }

    const float i0 = 1.f / l0;
    const float i1 = 1.f / l1;
    const int rb_t = b * 16 + qb;
    const uint32_t tbase = (uint32_t)(rb_t * NCHUNK + h) * TILE_B;
    const int rl0 = w * 16 + (lane >> 2);
#pragma unroll
    for (int nt = 0; nt < 8; nt++) {
        const int col2 = (nt * 8 + (lane & 3) * 2) * 2;
        uint32_t hi, lo;
        split2(o[nt][0] * i0, o[nt][1] * i0, hi, lo);
        uint32_t off = tbase + swz128((uint32_t)rl0 * 128 + col2);
        *(uint32_t*)((char*)ch + off) = hi;
        *(uint32_t*)((char*)cl + off) = lo;
        split2(o[nt][2] * i1, o[nt][3] * i1, hi, lo);
        off = tbase + swz128((uint32_t)(rl0 + 8) * 128 + col2);
        *(uint32_t*)((char*)ch + off) = hi;
        *(uint32_t*)((char*)cl + off) = lo;
    }
}

// ---------------------------------------------------------------------------
extern "C" void kernel_launch(void* const* d_in, const int* in_sizes, int n_in,
                              void* d_out, int out_size)
{
    const float* x  = (const float*)d_in[0];
    const float* Wq = (const float*)d_in[1];
    const float* Wk = (const float*)d_in[2];
    const float* Wv = (const float*)d_in[3];
    const float* Wo = (const float*)d_in[4];
    const float* bo = (const float*)d_in[5];
    float* out = (float*)d_out;

    __nv_bfloat16 *xh, *xl, *ch, *cl;
    __nv_bfloat16 *wqh, *wql, *wkh, *wkl, *wvh, *wvl, *woh, *wol;
    __nv_bfloat16 *qh, *ql, *kh, *kl, *vh, *vl;
    cudaGetSymbolAddress((void**)&xh,  g_xh);
    cudaGetSymbolAddress((void**)&xl,  g_xl);
    cudaGetSymbolAddress((void**)&ch,  g_ch);
    cudaGetSymbolAddress((void**)&cl,  g_cl);
    cudaGetSymbolAddress((void**)&wqh, g_wqh);
    cudaGetSymbolAddress((void**)&wql, g_wql);
    cudaGetSymbolAddress((void**)&wkh, g_wkh);
    cudaGetSymbolAddress((void**)&wkl, g_wkl);
    cudaGetSymbolAddress((void**)&wvh, g_wvh);
    cudaGetSymbolAddress((void**)&wvl, g_wvl);
    cudaGetSymbolAddress((void**)&woh, g_woh);
    cudaGetSymbolAddress((void**)&wol, g_wol);
    cudaGetSymbolAddress((void**)&qh,  g_qh);
    cudaGetSymbolAddress((void**)&ql,  g_ql);
    cudaGetSymbolAddress((void**)&kh,  g_kh);
    cudaGetSymbolAddress((void**)&kl,  g_kl);
    cudaGetSymbolAddress((void**)&vh,  g_vh);
    cudaGetSymbolAddress((void**)&vl,  g_vl);

    cudaFuncSetAttribute(gemm_qkv, cudaFuncAttributeMaxDynamicSharedMemorySize,
                         GSM_BYTES);
    cudaFuncSetAttribute(gemm_out, cudaFuncAttributeMaxDynamicSharedMemorySize,
                         GSM_BYTES);
    cudaFuncSetAttribute(flash_mma, cudaFuncAttributeMaxDynamicSharedMemorySize,
                         FSMEM);

    conv_act<<<2048, 256>>>(x, xh, xl);
    dim3 wg(512, 4);
    conv_w4<<<wg, 256>>>(Wq, Wk, Wv, Wo,
                         wqh, wql, wkh, wkl, wvh, wvl, woh, wol);

    dim3 gq(D_ / 128, NROW / 128, 3);   // (8, 64, 3)
    gemm_qkv<<<gq, 256, GSM_BYTES>>>(xh, xl,
                                     wqh, wql, wkh, wkl, wvh, wvl,
                                     qh, ql, kh, kl, vh, vl);

    dim3 fg(S_ / 128, H_, B_);          // (16, 16, 4)
    flash_mma<<<fg, 256, FSMEM>>>(qh, ql, kh, kl, vh, vl, ch, cl);

    dim3 gg(D_ / 128, NROW / 128);      // (8, 64)
    gemm_out<<<gg, 256, GSM_BYTES>>>(ch, cl, woh, wol, bo, out);
}

// round 16
// speedup vs baseline: 2.4974x; 2.4974x over previous
#include <cuda_runtime.h>
#include <cuda_fp16.h>
#include <math.h>
#include <stdint.h>

#define B_  4
#define S_  2048
#define D_  1024
#define H_  16
#define HD_ 64
#define NROW (B_*S_)          // 8192

#define TK      64
#define NCHUNK  (D_/TK)       // 16
#define TILE_B  16384         // bytes per 128-row x 128B tile (64 fp16 cols)

#define QSCALE 0.1803368801111601f   // 0.125 * log2(e)

// ---------------- scratch (static device globals; no allocation) ------------
__device__ __align__(128) __half g_x [NROW * D_];   // x tiled fp16
__device__ __align__(128) __half g_c [NROW * D_];   // ctx tiled fp16 (flash out)
__device__ __align__(128) __half g_wq[D_ * D_];
__device__ __align__(128) __half g_wk[D_ * D_];
__device__ __align__(128) __half g_wv[D_ * D_];
__device__ __align__(128) __half g_wo[D_ * D_];
__device__ __align__(128) __half g_q [NROW * D_];   // row-major fp16
__device__ __align__(128) __half g_k [NROW * D_];
__device__ __align__(128) __half g_v [NROW * D_];

// ---------------------------- helpers ---------------------------------------
__device__ __forceinline__ uint32_t smem_u32(const void* p) {
    uint32_t a;
    asm("{ .reg .u64 t; cvta.to.shared.u64 t, %1; cvt.u32.u64 %0, t; }"
        : "=r"(a) : "l"(p));
    return a;
}
__host__ __device__ __forceinline__ uint32_t swz128(uint32_t o) {
    return o ^ ((o >> 3) & 0x70);
}
__device__ __forceinline__ void cp16(uint32_t dst, const void* src) {
    asm volatile("cp.async.cg.shared.global [%0], [%1], 16;"
                 :: "r"(dst), "l"(src) : "memory");
}
__device__ __forceinline__ void cp_commit() {
    asm volatile("cp.async.commit_group;" ::: "memory");
}
template <int N>
__device__ __forceinline__ void cp_wait() {
    asm volatile("cp.async.wait_group %0;" :: "n"(N) : "memory");
}
__device__ __forceinline__ void ldm_x4(uint32_t* r, uint32_t addr) {
    asm volatile("ldmatrix.sync.aligned.m8n8.x4.shared.b16 {%0,%1,%2,%3}, [%4];"
                 : "=r"(r[0]), "=r"(r[1]), "=r"(r[2]), "=r"(r[3]) : "r"(addr));
}
__device__ __forceinline__ void ldm_x4t(uint32_t* r, uint32_t addr) {
    asm volatile("ldmatrix.sync.aligned.m8n8.x4.trans.shared.b16 {%0,%1,%2,%3}, [%4];"
                 : "=r"(r[0]), "=r"(r[1]), "=r"(r[2]), "=r"(r[3]) : "r"(addr));
}
__device__ __forceinline__ void mma16816(float* c, const uint32_t* a,
                                         const uint32_t* b) {
    asm volatile(
        "mma.sync.aligned.m16n8k16.row.col.f32.f16.f16.f32 "
        "{%0,%1,%2,%3}, {%4,%5,%6,%7}, {%8,%9}, {%0,%1,%2,%3};"
        : "+f"(c[0]), "+f"(c[1]), "+f"(c[2]), "+f"(c[3])
        : "r"(a[0]), "r"(a[1]), "r"(a[2]), "r"(a[3]), "r"(b[0]), "r"(b[1]));
}
__device__ __forceinline__ float ex2(float x) {
    float y;
    asm("ex2.approx.ftz.f32 %0, %1;" : "=f"(y) : "f"(x));
    return y;
}
__device__ __forceinline__ uint32_t pack2h(float a, float b) {
    __half2 h = __floats2half2_rn(a, b);   // a in low half
    return *reinterpret_cast<uint32_t*>(&h);
}

// ---------------------------------------------------------------------------
// Conversions: fp32 -> tiled/swizzled fp16
// ---------------------------------------------------------------------------
__global__ __launch_bounds__(256) void conv_act(const float* __restrict__ in,
                                                __half* __restrict__ o)
{
    const int base = blockIdx.x * 256 + threadIdx.x;   // grid 2048 -> 524288
#pragma unroll
    for (int jj = 0; jj < 2; jj++) {
        int idx = base + jj * 524288;
        int R  = idx >> 7, cb = idx & 127;
        int rb = R >> 7,  r  = R & 127;
        int kc = cb >> 3, cc = cb & 7;
        const float* p = in + (size_t)R * D_ + cb * 8;
        float4 a = *(const float4*)p;
        float4 b = *(const float4*)(p + 4);
        float v[8] = {a.x, a.y, a.z, a.w, b.x, b.y, b.z, b.w};
        union { __half h[8]; uint4 u; } uh;
#pragma unroll
        for (int j = 0; j < 8; j++) uh.h[j] = __float2half_rn(v[j]);
        uint32_t off = (uint32_t)(rb * NCHUNK + kc) * TILE_B + swz128(r * 128 + cc * 16);
        *(uint4*)((char*)o + off) = uh.u;
    }
}

// all four weights in one launch: blockIdx.y selects the matrix (transposed)
__global__ __launch_bounds__(256) void conv_w4(
    const float* __restrict__ W0, const float* __restrict__ W1,
    const float* __restrict__ W2, const float* __restrict__ W3,
    __half* __restrict__ o0, __half* __restrict__ o1,
    __half* __restrict__ o2, __half* __restrict__ o3)
{
    const int wsel = blockIdx.y;
    const float* W = (wsel == 0) ? W0 : (wsel == 1) ? W1 : (wsel == 2) ? W2 : W3;
    __half* o = (wsel == 0) ? o0 : (wsel == 1) ? o1 : (wsel == 2) ? o2 : o3;

    int idx = blockIdx.x * 256 + threadIdx.x;   // 131072
    int n  = idx & 1023, kb = idx >> 10;
    float v[8];
#pragma unroll
    for (int j = 0; j < 8; j++) v[j] = W[(size_t)(kb * 8 + j) * D_ + n];
    union { __half h[8]; uint4 u; } uh;
#pragma unroll
    for (int j = 0; j < 8; j++) uh.h[j] = __float2half_rn(v[j]);
    int tb = n >> 7, r = n & 127, kc = kb >> 3, cc = kb & 7;
    uint32_t off = (uint32_t)(tb * NCHUNK + kc) * TILE_B + swz128(r * 128 + cc * 16);
    *(uint4*)((char*)o + off) = uh.u;
}

// ---------------------------------------------------------------------------
// GEMM core — fp16 single-pass, 2-stage double-buffered (2x32KB, occ=2).
// ---------------------------------------------------------------------------
#define GSTG      32768
#define GSM_BYTES (2 * GSTG)   // 65536

__device__ __forceinline__ void gemm_core(
    uint32_t S0, const char* gA, const char* gB,
    int tid, int wid, int lane, float acc[4][4][4])
{
    const int wm = wid >> 2, wn = wid & 3;
    const int a_row = wm * 64 + (lane & 15);
    const int a_cb0 = (lane >> 4) * 16;
    const int b_idx = lane >> 3;
    const int b_row = wn * 32 + ((b_idx >> 1) * 8) + (lane & 7);
    const int b_cb0 = (b_idx & 1) * 16;

    // prologue: chunk 0 -> stage 0
#pragma unroll
    for (int i = tid; i < 1024; i += 256) {
        cp16(S0 + i * 16,         gA + i * 16);
        cp16(S0 + 16384 + i * 16, gB + i * 16);
    }
    cp_commit();

    for (int c = 0; c < NCHUNK; c++) {
        if (c + 1 < NCHUNK) {   // prefetch c+1 into the other stage
            const uint32_t st = S0 + (uint32_t)((c + 1) & 1) * GSTG;
            const uint32_t cofs = (uint32_t)(c + 1) * TILE_B;
#pragma unroll
            for (int i = tid; i < 1024; i += 256) {
                cp16(st + i * 16,         gA + cofs + i * 16);
                cp16(st + 16384 + i * 16, gB + cofs + i * 16);
            }
            cp_commit();
            cp_wait<1>();
        } else {
            cp_wait<0>();
        }
        __syncthreads();

        const uint32_t st = S0 + (uint32_t)(c & 1) * GSTG;
        const uint32_t SA = st, SB = st + 16384;

#pragma unroll
        for (int ks = 0; ks < 4; ks++) {
            uint32_t af[4][4], bf[4][2];
            const uint32_t acb = ks * 32 + a_cb0;
            const uint32_t bcb = ks * 32 + b_cb0;
#pragma unroll
            for (int i = 0; i < 4; i++)
                ldm_x4(af[i], SA + swz128((uint32_t)(a_row + i * 16) * 128 + acb));
#pragma unroll
            for (int jp = 0; jp < 2; jp++) {
                uint32_t t4[4];
                ldm_x4(t4, SB + swz128((uint32_t)(b_row + jp * 16) * 128 + bcb));
                bf[jp * 2 + 0][0] = t4[0]; bf[jp * 2 + 0][1] = t4[1];
                bf[jp * 2 + 1][0] = t4[2]; bf[jp * 2 + 1][1] = t4[3];
            }
#pragma unroll
            for (int i = 0; i < 4; i++)
#pragma unroll
                for (int j = 0; j < 4; j++) mma16816(acc[i][j], af[i], bf[j]);
        }
        __syncthreads();   // compute(c) done before next iter overwrites stage
    }
}

// Q/K/V in one launch: blockIdx.z selects weight + destination (+Q scale)
__global__ __launch_bounds__(256, 2) void gemm_qkv(
    const __half* __restrict__ A,
    const __half* __restrict__ wq, const __half* __restrict__ wk,
    const __half* __restrict__ wv,
    __half* __restrict__ q, __half* __restrict__ k, __half* __restrict__ v)
{
    extern __shared__ char sm[];
    const uint32_t S0 = smem_u32(sm);
    const int tid  = threadIdx.x;
    const int wid  = tid >> 5;
    const int lane = tid & 31;
    const int tb   = blockIdx.x;
    const int rb   = blockIdx.y;
    const int z    = blockIdx.z;

    const __half* Bm;
    __half* C;
    float osc;
    if (z == 0)      { Bm = wq; C = q; osc = QSCALE; }
    else if (z == 1) { Bm = wk; C = k; osc = 1.0f; }
    else             { Bm = wv; C = v; osc = 1.0f; }

    float acc[4][4][4];
#pragma unroll
    for (int i = 0; i < 4; i++)
#pragma unroll
        for (int j = 0; j < 4; j++)
#pragma unroll
            for (int r = 0; r < 4; r++) acc[i][j][r] = 0.f;

    gemm_core(S0,
              (const char*)A  + (size_t)rb * NCHUNK * TILE_B,
              (const char*)Bm + (size_t)tb * NCHUNK * TILE_B,
              tid, wid, lane, acc);

    const int wm = wid >> 2, wn = wid & 3;
    const int row0 = rb * 128 + wm * 64 + (lane >> 2);
    const int col0 = tb * 128 + wn * 32 + (lane & 3) * 2;
#pragma unroll
    for (int i = 0; i < 4; i++)
#pragma unroll
        for (int j = 0; j < 4; j++) {
            const int cc = col0 + j * 8;
            size_t p0 = ((size_t)(row0 + i * 16) * D_ + cc) * 2;
            size_t p1 = ((size_t)(row0 + i * 16 + 8) * D_ + cc) * 2;
            *(uint32_t*)((char*)C + p0) = pack2h(acc[i][j][0] * osc, acc[i][j][1] * osc);
            *(uint32_t*)((char*)C + p1) = pack2h(acc[i][j][2] * osc, acc[i][j][3] * osc);
        }
}

// output projection: fp32 epilogue + bias
__global__ __launch_bounds__(256, 2) void gemm_out(
    const __half* __restrict__ A, const __half* __restrict__ Bm,
    const float* __restrict__ bias, float* __restrict__ C)
{
    extern __shared__ char sm[];
    const uint32_t S0 = smem_u32(sm);
    const int tid  = threadIdx.x;
    const int wid  = tid >> 5;
    const int lane = tid & 31;
    const int tb   = blockIdx.x;
    const int rb   = blockIdx.y;

    float acc[4][4][4];
#pragma unroll
    for (int i = 0; i < 4; i++)
#pragma unroll
        for (int j = 0; j < 4; j++)
#pragma unroll
            for (int r = 0; r < 4; r++) acc[i][j][r] = 0.f;

    gemm_core(S0,
              (const char*)A  + (size_t)rb * NCHUNK * TILE_B,
              (const char*)Bm + (size_t)tb * NCHUNK * TILE_B,
              tid, wid, lane, acc);

    const int wm = wid >> 2, wn = wid & 3;
    const int row0 = rb * 128 + wm * 64 + (lane >> 2);
    const int col0 = tb * 128 + wn * 32 + (lane & 3) * 2;
#pragma unroll
    for (int i = 0; i < 4; i++)
#pragma unroll
        for (int j = 0; j < 4; j++) {
            const int cc = col0 + j * 8;
            const float b0 = bias[cc], b1 = bias[cc + 1];
            float* p0 = C + (size_t)(row0 + i * 16) * D_ + cc;
            float* p1 = C + (size_t)(row0 + i * 16 + 8) * D_ + cc;
            *(float2*)p0 = make_float2(acc[i][j][0] + b0, acc[i][j][1] + b1);
            *(float2*)p1 = make_float2(acc[i][j][2] + b0, acc[i][j][3] + b1);
        }
}

// ---------------------------------------------------------------------------
// Flash attention, fp16 single-pass. smem: Q 16KB + 2 stages x (K 8KB + V 8KB).
// ---------------------------------------------------------------------------
#define FSMEM (16384 + 32768)

__device__ __forceinline__ void fa_load_stage(
    uint32_t sst, int st, int jb, int tid, size_t rowoff_base,
    const __half* k, const __half* v)
{
    const int r  = tid >> 2;          // 0..63
    const int u0 = (tid & 3) * 2;     // 0,2,4,6
    const size_t rowoff = rowoff_base + (size_t)(jb * 64 + r) * 2048;
    const uint32_t base = sst + st * 16384;
    const char* s0 = (const char*)k + rowoff;
    const char* s1 = (const char*)v + rowoff;
#pragma unroll
    for (int uu = 0; uu < 2; uu++) {
        const uint32_t d = swz128(r * 128 + (u0 + uu) * 16);
        const int sb = (u0 + uu) * 16;
        cp16(base + d,        s0 + sb);
        cp16(base + 8192 + d, s1 + sb);
    }
}

__global__ __launch_bounds__(256, 2) void flash_mma(
    const __half* __restrict__ q, const __half* __restrict__ k,
    const __half* __restrict__ v, __half* __restrict__ ctx)
{
    extern __shared__ char sm[];
    const uint32_t SQ  = smem_u32(sm);
    const uint32_t SST = SQ + 16384;

    const int tid  = threadIdx.x;
    const int w    = tid >> 5;
    const int lane = tid & 31;
    const int qb   = 15 - blockIdx.x;
    const int h    = blockIdx.y;
    const int b    = blockIdx.z;
    const int qbase = qb * 128;
    const size_t seqoff = ((size_t)b * 2048) * 2048 + (size_t)h * 128;  // bytes

    // Q tile: 128 rows x 128B
    {
        const int r  = tid >> 1;
        const int u0 = (tid & 1) * 4;
        const size_t ro = seqoff + (size_t)(qbase + r) * 2048;
        const char* s = (const char*)q + ro;
#pragma unroll
        for (int u = u0; u < u0 + 4; u++)
            cp16(SQ + swz128(r * 128 + u * 16), s + u * 16);
    }
    cp_commit();

    const int nkb = 2 * qb + 2;
    fa_load_stage(SST, 0, 0, tid, seqoff, k, v);
    cp_commit();
    cp_wait<0>();
    __syncthreads();

    uint32_t aq[4][4];
    {
        const int ar = w * 16 + (lane & 15);
        const int acb = (lane >> 4) * 16;
#pragma unroll
        for (int kt = 0; kt < 4; kt++)
            ldm_x4(aq[kt], SQ + swz128((uint32_t)ar * 128 + kt * 32 + acb));
    }

    float o[8][4];
#pragma unroll
    for (int n = 0; n < 8; n++)
#pragma unroll
        for (int r = 0; r < 4; r++) o[n][r] = 0.f;
    float m0 = -INFINITY, m1 = -INFINITY, l0 = 0.f, l1 = 0.f;

    const int wrow0 = qbase + w * 16;

    for (int jb = 0; jb < nkb; jb++) {
        if (jb + 1 < nkb) {
            fa_load_stage(SST, (jb + 1) & 1, jb + 1, tid, seqoff, k, v);
            cp_commit();
            cp_wait<1>();
        } else {
            cp_wait<0>();
        }
        __syncthreads();

        const int kbase = jb * 64;
        if (kbase <= wrow0 + 15) {
            const uint32_t base = SST + (uint32_t)(jb & 1) * 16384;
            const uint32_t KH = base, VH = base + 8192;

            float sacc[8][4];
#pragma unroll
            for (int n = 0; n < 8; n++)
#pragma unroll
                for (int r = 0; r < 4; r++) sacc[n][r] = 0.f;

            const uint32_t krow = ((lane >> 4) & 1) * 8 + (lane & 7);
            const uint32_t kcb  = ((lane >> 3) & 1) * 16;
#pragma unroll
            for (int kt = 0; kt < 4; kt++) {
#pragma unroll
                for (int ntp = 0; ntp < 4; ntp++) {
                    uint32_t b4[4];
                    ldm_x4(b4, KH + swz128((ntp * 16 + krow) * 128 + kt * 32 + kcb));
                    mma16816(sacc[2 * ntp],     aq[kt], b4 + 0);
                    mma16816(sacc[2 * ntp + 1], aq[kt], b4 + 2);
                }
            }

            if (kbase + 63 > wrow0) {
                const int rg = wrow0 + (lane >> 2);
#pragma unroll
                for (int nt = 0; nt < 8; nt++) {
                    const int cg = kbase + nt * 8 + (lane & 3) * 2;
                    if (cg     > rg)     sacc[nt][0] = -INFINITY;
                    if (cg + 1 > rg)     sacc[nt][1] = -INFINITY;
                    if (cg     > rg + 8) sacc[nt][2] = -INFINITY;
                    if (cg + 1 > rg + 8) sacc[nt][3] = -INFINITY;
                }
            }

            float nm0 = m0, nm1 = m1;
#pragma unroll
            for (int nt = 0; nt < 8; nt++) {
                nm0 = fmaxf(nm0, fmaxf(sacc[nt][0], sacc[nt][1]));
                nm1 = fmaxf(nm1, fmaxf(sacc[nt][2], sacc[nt][3]));
            }
            nm0 = fmaxf(nm0, __shfl_xor_sync(0xffffffffu, nm0, 1));
            nm0 = fmaxf(nm0, __shfl_xor_sync(0xffffffffu, nm0, 2));
            nm1 = fmaxf(nm1, __shfl_xor_sync(0xffffffffu, nm1, 1));
            nm1 = fmaxf(nm1, __shfl_xor_sync(0xffffffffu, nm1, 2));

            const float sc0 = ex2(m0 - nm0);
            const float sc1 = ex2(m1 - nm1);
            m0 = nm0; m1 = nm1;
            l0 *= sc0; l1 *= sc1;
#pragma unroll
            for (int nt = 0; nt < 8; nt++) {
                o[nt][0] *= sc0; o[nt][1] *= sc0;
                o[nt][2] *= sc1; o[nt][3] *= sc1;
            }

            float rs0 = 0.f, rs1 = 0.f;
            uint32_t ph[4][4];
#pragma unroll
            for (int t = 0; t < 4; t++) {
#pragma unroll
                for (int hh = 0; hh < 2; hh++) {
                    const int nt = 2 * t + hh;
                    const float p0 = ex2(sacc[nt][0] - nm0);
                    const float p1 = ex2(sacc[nt][1] - nm0);
                    const float p2 = ex2(sacc[nt][2] - nm1);
                    const float p3 = ex2(sacc[nt][3] - nm1);
                    rs0 += p0 + p1; rs1 += p2 + p3;
                    ph[t][2 * hh + 0] = pack2h(p0, p1);
                    ph[t][2 * hh + 1] = pack2h(p2, p3);
                }
            }
            rs0 += __shfl_xor_sync(0xffffffffu, rs0, 1);
            rs0 += __shfl_xor_sync(0xffffffffu, rs0, 2);
            rs1 += __shfl_xor_sync(0xffffffffu, rs1, 1);
            rs1 += __shfl_xor_sync(0xffffffffu, rs1, 2);
            l0 += rs0; l1 += rs1;

            const uint32_t vrow = lane & 15;
            const uint32_t vcg  = lane >> 4;
#pragma unroll
            for (int kt = 0; kt < 4; kt++) {
#pragma unroll
                for (int ntp = 0; ntp < 4; ntp++) {
                    uint32_t b4[4];
                    ldm_x4t(b4, VH + swz128((kt * 16 + vrow) * 128 + (2 * ntp + vcg) * 16));
                    mma16816(o[2 * ntp],     ph[kt], b4 + 0);
                    mma16816(o[2 * ntp + 1], ph[kt], b4 + 2);
                }
            }
        }
        __syncthreads();
    }

    // normalize; write ctx in tiled/swizzled fp16 for gemm_out
    const float i0 = 1.f / l0;
    const float i1 = 1.f / l1;
    const int rb_t = b * 16 + qb;
    const uint32_t tbase = (uint32_t)(rb_t * NCHUNK + h) * TILE_B;
    const int rl0 = w * 16 + (lane >> 2);
#pragma unroll
    for (int nt = 0; nt < 8; nt++) {
        const int col2 = (nt * 8 + (lane & 3) * 2) * 2;
        uint32_t off = tbase + swz128((uint32_t)rl0 * 128 + col2);
        *(uint32_t*)((char*)ctx + off) = pack2h(o[nt][0] * i0, o[nt][1] * i0);
        off = tbase + swz128((uint32_t)(rl0 + 8) * 128 + col2);
        *(uint32_t*)((char*)ctx + off) = pack2h(o[nt][2] * i1, o[nt][3] * i1);
    }
}

// ---------------------------------------------------------------------------
extern "C" void kernel_launch(void* const* d_in, const int* in_sizes, int n_in,
                              void* d_out, int out_size)
{
    const float* x  = (const float*)d_in[0];
    const float* Wq = (const float*)d_in[1];
    const float* Wk = (const float*)d_in[2];
    const float* Wv = (const float*)d_in[3];
    const float* Wo = (const float*)d_in[4];
    const float* bo = (const float*)d_in[5];
    float* out = (float*)d_out;

    __half *xh, *ch, *wq, *wk, *wv, *wo, *q, *k, *v;
    cudaGetSymbolAddress((void**)&xh, g_x);
    cudaGetSymbolAddress((void**)&ch, g_c);
    cudaGetSymbolAddress((void**)&wq, g_wq);
    cudaGetSymbolAddress((void**)&wk, g_wk);
    cudaGetSymbolAddress((void**)&wv, g_wv);
    cudaGetSymbolAddress((void**)&wo, g_wo);
    cudaGetSymbolAddress((void**)&q,  g_q);
    cudaGetSymbolAddress((void**)&k,  g_k);
    cudaGetSymbolAddress((void**)&v,  g_v);

    cudaFuncSetAttribute(gemm_qkv, cudaFuncAttributeMaxDynamicSharedMemorySize,
                         GSM_BYTES);
    cudaFuncSetAttribute(gemm_out, cudaFuncAttributeMaxDynamicSharedMemorySize,
                         GSM_BYTES);
    cudaFuncSetAttribute(flash_mma, cudaFuncAttributeMaxDynamicSharedMemorySize,
                         FSMEM);

    conv_act<<<2048, 256>>>(x, xh);
    dim3 wg(512, 4);
    conv_w4<<<wg, 256>>>(Wq, Wk, Wv, Wo, wq, wk, wv, wo);

    dim3 gq(D_ / 128, NROW / 128, 3);   // (8, 64, 3)
    gemm_qkv<<<gq, 256, GSM_BYTES>>>(xh, wq, wk, wv, q, k, v);

    dim3 fg(S_ / 128, H_, B_);          // (16, 16, 4)
    flash_mma<<<fg, 256, FSMEM>>>(q, k, v, ch);

    dim3 gg(D_ / 128, NROW / 128);      // (8, 64)
    gemm_out<<<gg, 256, GSM_BYTES>>>(ch, wo, bo, out);
}